// round 12
// baseline (speedup 1.0000x reference)
#include <cuda_runtime.h>
#include <cstdint>

// Problem constants
#define B_SZ   1024
#define F_SZ   784
#define OUT_F  1024
#define OR_T   32
#define AND_T  16
#define NROWS  785               // positive literals: idx 0 (const-true) + x[0..783]
#define HBG    16                // batch-groups per half (512 batches)

// Single-polarity table, split in batch halves for linear bulk copy:
// g_P[h][idx][bg16]  (word offset = h*NROWS*HBG + idx*HBG + bg)
#define HALF_WORDS (NROWS * HBG)             // 12560 words = 50240 B
__device__ __align__(16) uint32_t g_P[2 * HALF_WORDS];

// ---------------------------------------------------------------------------
// Pack kernel: grid (25, 32), 128 threads. Coalesced 32x32 tile load ->
// smem transpose -> ballot -> single-polarity table write.
// ---------------------------------------------------------------------------
__global__ __launch_bounds__(128) void pack_kernel(const float* __restrict__ x) {
    __shared__ float tile[32][33];

    const int ft  = blockIdx.x;
    const int bg  = blockIdx.y;               // 0..31
    const int tid = threadIdx.x;
    const int f0  = ft * 32;

    const int c  = tid & 31;
    const int r0 = tid >> 5;
    #pragma unroll
    for (int r = r0; r < 32; r += 4) {
        const int f = f0 + c;
        tile[r][c] = (f < F_SZ) ? x[(size_t)(bg * 32 + r) * F_SZ + f] : 0.0f;
    }
    __syncthreads();

    const int h    = bg >> 4;
    const int bgl  = bg & 15;
    uint32_t* base = g_P + (size_t)h * HALF_WORDS + bgl;

    const int lane = tid & 31;
    const int w    = tid >> 5;
    #pragma unroll
    for (int ff = w; ff < 32; ff += 4) {
        const int f = f0 + ff;
        if (f >= F_SZ) break;
        uint32_t m = __ballot_sync(0xFFFFFFFFu, tile[lane][ff] != 0.0f);
        if (lane == 0) base[(size_t)(1 + f) * HBG] = m;
    }
    if (ft == 0 && tid == 0) base[0] = 0xFFFFFFFFu;   // const-true row
}

// ---------------------------------------------------------------------------
// Logic kernel: grid (128 output-slices, 2 batch-halves) x 512 threads.
//  - 50KB single-polarity table half via TMA bulk copy (5 x 10048B chunks;
//    10048 = 16*628, so every chunk src/dst stays 16B-aligned).
//  - Negated literals computed inline: row[idx - (neg & 784)] ^ neg_mask.
//  - Warp = (output o = wid>>1, term-half th = wid&1). Lane = (t2 = lane>>4
//    term-of-pair, bg = lane&15). 8 passes x 2 terms cover th's 16 terms.
// ---------------------------------------------------------------------------
#define OPB 8
#define NTHREADS 512
#define W_WORDS (OPB * OR_T * AND_T)                  // 4096 words = 16 KB
#define RES_WORDS (OPB * 2 * HBG)                     // 256 words
#define MBAR_OFF_W (HALF_WORDS + W_WORDS + RES_WORDS) // 16912 words (8B aligned)
#define SMEM_BYTES ((MBAR_OFF_W + 4) * 4)             // 67664 B
#define HALF_BYTES (HALF_WORDS * 4)                   // 50240
#define N_CHUNKS    5
#define CHUNK_BYTES (HALF_BYTES / N_CHUNKS)           // 10048 = 16 * 628

__global__ __launch_bounds__(NTHREADS) void logic_kernel(
    const int* __restrict__ weights, float* __restrict__ out) {

    extern __shared__ uint32_t smem[];
    uint32_t* sP   = smem;                      // table half (12560 words)
    uint32_t* sw   = smem + HALF_WORDS;         // weights (4096 words)
    uint32_t* resb = sw + W_WORDS;              // results [o][th][bg]
    uint32_t  mbar_addr;
    {
        uint64_t* mb64 = (uint64_t*)(smem + MBAR_OFF_W);
        asm("{ .reg .u64 t; cvta.to.shared.u64 t, %1; cvt.u32.u64 %0, t; }"
            : "=r"(mbar_addr) : "l"((void*)mb64));
    }

    const int tid   = threadIdx.x;
    const int oBase = blockIdx.x * OPB;
    const int h     = blockIdx.y;               // batch half

    if (tid == 0) {
        asm volatile("mbarrier.init.shared.b64 [%0], 1;" :: "r"(mbar_addr) : "memory");
    }
    __syncthreads();

    if (tid == 0) {
        asm volatile("mbarrier.arrive.expect_tx.shared.b64 _, [%0], %1;"
                     :: "r"(mbar_addr), "r"((uint32_t)HALF_BYTES) : "memory");
        const char* gsrc = (const char*)(g_P + (size_t)h * HALF_WORDS);
        uint32_t sdst;
        asm("{ .reg .u64 t; cvta.to.shared.u64 t, %1; cvt.u32.u64 %0, t; }"
            : "=r"(sdst) : "l"((void*)sP));
        #pragma unroll
        for (int i = 0; i < N_CHUNKS; ++i) {
            asm volatile(
                "cp.async.bulk.shared::cta.global.mbarrier::complete_tx::bytes "
                "[%0], [%1], %2, [%3];"
                :: "r"(sdst + i * CHUNK_BYTES), "l"(gsrc + (size_t)i * CHUNK_BYTES),
                   "r"((uint32_t)CHUNK_BYTES), "r"(mbar_addr) : "memory");
        }
    }

    // Stage weights while DMA runs (2 uint4 per thread, coalesced)
    {
        const uint4* wsrc = (const uint4*)(weights + (size_t)oBase * OR_T * AND_T);
        uint4* wdst = (uint4*)sw;
        wdst[tid]            = wsrc[tid];
        wdst[tid + NTHREADS] = wsrc[tid + NTHREADS];
    }
    __syncthreads();

    // Wait for the table half
    {
        uint32_t done;
        asm volatile(
            "{\n\t.reg .pred p;\n\t"
            "mbarrier.try_wait.parity.acquire.cta.shared::cta.b64 p, [%1], 0;\n\t"
            "selp.b32 %0, 1, 0, p;\n\t}"
            : "=r"(done) : "r"(mbar_addr) : "memory");
        if (!done) {
            asm volatile(
                "{\n\t.reg .pred P1;\n\t"
                "WL_%=:\n\t"
                "mbarrier.try_wait.parity.acquire.cta.shared::cta.b64 P1, [%0], 0, 0x989680;\n\t"
                "@P1 bra.uni WD_%=;\n\t"
                "bra.uni WL_%=;\n\t"
                "WD_%=:\n\t}"
                :: "r"(mbar_addr) : "memory");
        }
    }

    const int wid  = tid >> 5;                  // 0..15
    const int lane = tid & 31;
    const int o    = wid >> 1;                  // output within block (0..7)
    const int th   = wid & 1;                   // term half (16 terms)
    const int t2   = lane >> 4;                 // term within pair
    const int bg   = lane & 15;                 // local batch-group

    const uint32_t* swb = sw + o * (OR_T * AND_T);

    // Gather with inline negation: idx>784 -> row (idx-784) XOR ~0
    #define GV(i, acc) do {                                                   \
        const uint32_t _i  = (i);                                             \
        const uint32_t _xm = (_i > 784u) ? 0xFFFFFFFFu : 0u;                  \
        const uint32_t _e  = _i - (_xm & 784u);                               \
        (acc) &= (sP[_e * HBG + bg] ^ _xm);                                   \
    } while (0)

    uint32_t res = 0;
    #pragma unroll
    for (int p = 0; p < 8; ++p) {
        const int term = th * 16 + p * 2 + t2;
        const uint4* tw4 = (const uint4*)(swb + term * AND_T);
        uint32_t m0 = ~0u, m1 = ~0u;
        uint32_t orw = 0;
        #pragma unroll
        for (int k4 = 0; k4 < 4; ++k4) {
            const uint4 w4 = tw4[k4];           // LDS.128, uniform per 16 lanes
            orw |= (w4.x | w4.y | w4.z | w4.w);
            GV(w4.x, m0);
            GV(w4.y, m1);
            GV(w4.z, m0);
            GV(w4.w, m1);
        }
        if (orw != 0) res |= (m0 & m1);
    }
    #undef GV

    // OR across the term pair (lanes +-16 share bg)
    res |= __shfl_xor_sync(0xFFFFFFFFu, res, 16);
    if (lane < 16) resb[(o * 2 + th) * HBG + bg] = res;
    __syncthreads();

    // Store: thread = local batch (512); 8 contiguous floats (two float4)
    {
        const int b    = tid;
        const int lbg  = b >> 5;
        const int j    = b & 31;
        const int gb   = h * 512 + b;
        float4 v0, v1;
        #define GETBIT(ow) ((((resb[((ow)*2+0)*HBG + lbg] | \
                               resb[((ow)*2+1)*HBG + lbg]) >> j) & 1u))
        v0.x = (float)GETBIT(0); v0.y = (float)GETBIT(1);
        v0.z = (float)GETBIT(2); v0.w = (float)GETBIT(3);
        v1.x = (float)GETBIT(4); v1.y = (float)GETBIT(5);
        v1.z = (float)GETBIT(6); v1.w = (float)GETBIT(7);
        #undef GETBIT
        float4* dst = (float4*)(out + (size_t)gb * OUT_F + oBase);
        dst[0] = v0;
        dst[1] = v1;
    }
}

// ---------------------------------------------------------------------------
extern "C" void kernel_launch(void* const* d_in, const int* in_sizes, int n_in,
                              void* d_out, int out_size) {
    const float* x       = (const float*)d_in[0];   // (1024, 784) float32
    const int*   weights = (const int*)d_in[1];     // (1024, 32, 16) int32
    float*       out     = (float*)d_out;           // (1024, 1024) float32

    cudaFuncSetAttribute(logic_kernel,
                         cudaFuncAttributeMaxDynamicSharedMemorySize, SMEM_BYTES);

    dim3 pgrid(25, 32);
    pack_kernel<<<pgrid, 128>>>(x);
    dim3 lgrid(OUT_F / OPB, 2);                 // (128, 2) = 256 CTAs
    logic_kernel<<<lgrid, NTHREADS, SMEM_BYTES>>>(weights, out);
}